// round 17
// baseline (speedup 1.0000x reference)
#include <cuda_runtime.h>
#include <cuda_bf16.h>
#include <stdint.h>

// R17: R16 bisection kernel + the W1 staging fix (TPB=256 but W1 has 384
// entries -- the old `if (tid < 384)` left W1s[256..383] as garbage, which
// was the sole source of the rel_err ~ 1.06 in R14/R16).
// Layer 2 via mma.sync bf16 3-term split; downstream scalar (R3-proven):
// mma D -> transposed smem DT[col][row] -> LDS.128 gives {u,udz,udt,udzz} ->
// tanh-JVP -> R3-format float2 pairs -> layer 3+4 via proven FFMA2 path.
// Rows: R = 4*p + q. Split-bf16: X*W ~ Xh*Wh + Xh*Wl + Xl*Wh.

#define TPB 256
#define NSM 148
#define PAD 136          // bf16 row stride for mma tiles
#define DTP 132          // fp32 row stride for DT scratch

typedef unsigned int u32;
typedef unsigned long long ull;

#define W2H_OFF 0        // bf16[128][136] = 34816 B
#define W2L_OFF 34816
#define A0H_OFF 69632    // 34816 B
#define A0L_OFF 104448   // ends 139264
#define DT_OFF  69632    // fp32[128][132] = 67584 B, overlays A0 after mma
#define AP_OFF  139264   // float2[128][32] = 32768
#define BP_OFF  172032   // 32768, ends 204800
#define CONST_OFF 204800 // W1s(384f) b1s(128f) b2s(128f) b3s(64f) W4s(64f)
#define SMEM_TOTAL 207872

__device__ __forceinline__ float fast_tanh(float u) {
    float e, r;
    asm("ex2.approx.f32 %0, %1;" : "=f"(e) : "f"(u * 2.8853900817779268f));
    asm("rcp.approx.f32 %0, %1;" : "=f"(r) : "f"(e + 1.0f));
    return fmaf(-2.0f, r, 1.0f);
}
__device__ __forceinline__ u32 split_pair(float r0, float r1, u32* lo_out) {
    __nv_bfloat16 h0 = __float2bfloat16(r0);
    __nv_bfloat16 h1 = __float2bfloat16(r1);
    __nv_bfloat16 l0 = __float2bfloat16(r0 - __bfloat162float(h0));
    __nv_bfloat16 l1 = __float2bfloat16(r1 - __bfloat162float(h1));
    *lo_out = (u32)__bfloat16_as_ushort(l0) | ((u32)__bfloat16_as_ushort(l1) << 16);
    return (u32)__bfloat16_as_ushort(h0) | ((u32)__bfloat16_as_ushort(h1) << 16);
}
__device__ __forceinline__ void mma_bf16(float d[4], u32 a0, u32 a1, u32 a2, u32 a3,
                                         u32 b0, u32 b1) {
    asm volatile(
        "mma.sync.aligned.m16n8k16.row.col.f32.bf16.bf16.f32 "
        "{%0,%1,%2,%3}, {%4,%5,%6,%7}, {%8,%9}, {%0,%1,%2,%3};"
        : "+f"(d[0]), "+f"(d[1]), "+f"(d[2]), "+f"(d[3])
        : "r"(a0), "r"(a1), "r"(a2), "r"(a3), "r"(b0), "r"(b1));
}
__device__ __forceinline__ ull ffma2(ull a, ull b, ull c) {
    ull d;
    asm("fma.rn.f32x2 %0, %1, %2, %3;" : "=l"(d) : "l"(a), "l"(b), "l"(c));
    return d;
}
__device__ __forceinline__ ull pack2(float lo, float hi) {
    ull v;
    asm("mov.b64 %0, {%1, %2};" : "=l"(v) : "f"(lo), "f"(hi));
    return v;
}
__device__ __forceinline__ float2 unpack2(ull v) {
    float2 r;
    asm("mov.b64 {%0, %1}, %2;" : "=f"(r.x), "=f"(r.y) : "l"(v));
    return r;
}
__device__ __forceinline__ void tanh_jvp_pk(ull u01, ull u23, ull* h01, ull* h23) {
    float2 v01 = unpack2(u01);
    float2 v23 = unpack2(u23);
    float h = fast_tanh(v01.x);
    float s = 1.0f - h * h;
    float hdz  = s * v01.y;
    float hdt  = s * v23.x;
    float hdzz = fmaf(-2.0f * h * hdz, v01.y, s * v23.y);
    *h01 = pack2(h, hdz);
    *h23 = pack2(hdt, hdzz);
}

__global__ __launch_bounds__(TPB, 1)
void pinn_tc2_kernel(const float* __restrict__ x,
                     const float* __restrict__ W1, const float* __restrict__ b1,
                     const float* __restrict__ W2, const float* __restrict__ b2,
                     const float* __restrict__ W3, const float* __restrict__ b3,
                     const float* __restrict__ W4, const float* __restrict__ b4,
                     float* __restrict__ out, int n_tiles)
{
    extern __shared__ char smem[];
    __nv_bfloat16* W2h = (__nv_bfloat16*)(smem + W2H_OFF);
    __nv_bfloat16* W2l = (__nv_bfloat16*)(smem + W2L_OFF);
    __nv_bfloat16* A0h = (__nv_bfloat16*)(smem + A0H_OFF);
    __nv_bfloat16* A0l = (__nv_bfloat16*)(smem + A0L_OFF);
    float*  DT = (float*)(smem + DT_OFF);
    float2* Ap = (float2*)(smem + AP_OFF);
    float2* Bp = (float2*)(smem + BP_OFF);
    float* W1s = (float*)(smem + CONST_OFF);   // [3][128]
    float* b1s = W1s + 384;
    float* b2s = b1s + 128;
    float* b3s = b2s + 128;
    float* W4s = b3s + 64;

    const int tid  = threadIdx.x;
    const int lane = tid & 31;
    const int warp = tid >> 5;            // 0..7

    // ---- stage W2 (transposed, split) + consts, ONCE ----
    for (int idx = tid; idx < 128 * 128; idx += TPB) {
        int k = idx >> 7, n = idx & 127;               // W2[k][n]
        float w = __ldg(&W2[idx]);
        __nv_bfloat16 hi = __float2bfloat16(w);
        __nv_bfloat16 lo = __float2bfloat16(w - __bfloat162float(hi));
        W2h[n * PAD + k] = hi;  W2l[n * PAD + k] = lo;
    }
    // FIX: W1 has 384 entries but TPB=256 -- must LOOP (R14/R16 left
    // W1s[256..383] unwritten => garbage theta-weights => rel_err ~ 1).
    for (int i = tid; i < 384; i += TPB) W1s[i] = __ldg(&W1[i]);
    if (tid < 128) { b1s[tid] = __ldg(&b1[tid]); b2s[tid] = __ldg(&b2[tid]); }
    if (tid < 64)  { b3s[tid] = __ldg(&b3[tid]); W4s[tid] = __ldg(&W4[tid]); }
    __syncthreads();

    const int r4 = lane >> 2;             // 0..7
    const int m  = lane & 3;              // 0..3
    const int R0 = warp * 16;             // warp's 16-row slab
    const float b4v = __ldg(&b4[0]);

    for (int tile = blockIdx.x; tile < n_tiles; tile += NSM) {

        // ---------- Layer 1: 3 -> 128, warp writes its 16 rows of A0 ------
        {
            int r16 = lane & 15;
            int R   = R0 + r16;
            int ch  = lane >> 4;                        // column half
            int pg  = tile * 32 + (R >> 2);
            int qq  = R & 3;
            float x0 = __ldg(&x[pg * 3 + 0]);
            float x1 = __ldg(&x[pg * 3 + 1]);
            float x2 = __ldg(&x[pg * 3 + 2]);
            __nv_bfloat16* dh = A0h + R * PAD + ch * 64;
            __nv_bfloat16* dl = A0l + R * PAD + ch * 64;
            #pragma unroll 4
            for (int jj = 0; jj < 64; jj += 2) {
                float rv[2];
                #pragma unroll
                for (int t = 0; t < 2; t++) {
                    int j = ch * 64 + jj + t;
                    float w0 = W1s[j], w1 = W1s[128 + j], w2 = W1s[256 + j];
                    float u = fmaf(x0, w0, fmaf(x1, w1, fmaf(x2, w2, b1s[j])));
                    float h = fast_tanh(u);
                    float s = 1.0f - h * h;
                    float r;
                    if      (qq == 0) r = h;
                    else if (qq == 1) r = s * w0;
                    else if (qq == 2) r = s * w1;
                    else              r = -2.0f * h * (s * w0) * w0;
                    rv[t] = r;
                }
                u32 lo, hi = split_pair(rv[0], rv[1], &lo);
                *(u32*)(dh + jj) = hi;
                *(u32*)(dl + jj) = lo;
            }
        }
        __syncwarp();

        // ---------- Layer 2 mma: D[16,128] = A0 * W2 (3 splits) -----------
        float d[16][4];
        #pragma unroll
        for (int nt = 0; nt < 16; nt++)
            d[nt][0] = d[nt][1] = d[nt][2] = d[nt][3] = 0.0f;
        #pragma unroll 1
        for (int s = 0; s < 3; s++) {
            const __nv_bfloat16* Ab = (s == 2) ? A0l : A0h;
            const __nv_bfloat16* Bb = (s == 1) ? W2l : W2h;
            const __nv_bfloat16* Arow = Ab + (R0 + r4) * PAD + m * 2;
            const __nv_bfloat16* Brow = Bb + r4 * PAD + m * 2;
            #pragma unroll 2
            for (int kb = 0; kb < 8; kb++) {
                int ko = kb * 16;
                u32 a0 = *(const u32*)(Arow + ko);
                u32 a1 = *(const u32*)(Arow + 8 * PAD + ko);
                u32 a2 = *(const u32*)(Arow + ko + 8);
                u32 a3 = *(const u32*)(Arow + 8 * PAD + ko + 8);
                #pragma unroll
                for (int nt = 0; nt < 16; nt++) {
                    u32 b0  = *(const u32*)(Brow + nt * 8 * PAD + ko);
                    u32 b1v = *(const u32*)(Brow + nt * 8 * PAD + ko + 8);
                    mma_bf16(d[nt], a0, a1, a2, a3, b0, b1v);
                }
            }
        }
        __syncthreads();   // ALL warps done reading A0 (DT overlays it)

        // ---------- dump D -> DT[col][row] ----------------
        #pragma unroll
        for (int nt = 0; nt < 16; nt++) {
            int j0 = nt * 8 + m * 2;
            DT[j0 * DTP + R0 + r4]           = d[nt][0];
            DT[(j0 + 1) * DTP + R0 + r4]     = d[nt][1];
            DT[j0 * DTP + R0 + r4 + 8]       = d[nt][2];
            DT[(j0 + 1) * DTP + R0 + r4 + 8] = d[nt][3];
        }
        __syncthreads();

        // ---------- convert: tanh-JVP, write R3-format pairs --------------
        #pragma unroll 4
        for (int i = 0; i < 16; i++) {
            int task = tid + i * TPB;
            int j = task >> 5, p = task & 31;
            float4 v = *(const float4*)(DT + j * DTP + 4 * p);
            float u = v.x + b2s[j];
            float h = fast_tanh(u);
            float s = 1.0f - h * h;
            float hdz  = s * v.y;
            float hdt  = s * v.z;
            float hdzz = fmaf(-2.0f * h * hdz, v.y, s * v.w);
            Ap[j * 32 + p] = make_float2(h, hdz);
            Bp[j * 32 + p] = make_float2(hdt, hdzz);
        }
        __syncthreads();

        // ---------- Layer 3: 128 -> 64, proven FFMA2 path -----------------
        {
            const int j0 = warp * 8;
            ull acc01[8], acc23[8];
            #pragma unroll
            for (int c = 0; c < 8; c++) {
                acc01[c] = pack2(b3s[j0 + c], 0.0f);
                acc23[c] = 0ULL;
            }
            const ull* aA = (const ull*)Ap + lane;
            const ull* aB = (const ull*)Bp + lane;
            #pragma unroll 2
            for (int k = 0; k < 128; k++) {
                ull a01 = aA[k * 32];
                ull a23 = aB[k * 32];
                float4 wA = __ldg((const float4*)(W3 + k * 64 + j0));
                float4 wB = __ldg((const float4*)(W3 + k * 64 + j0 + 4));
                ull w0 = pack2(wA.x, wA.x), w1 = pack2(wA.y, wA.y);
                ull w2 = pack2(wA.z, wA.z), w3 = pack2(wA.w, wA.w);
                ull w4 = pack2(wB.x, wB.x), w5 = pack2(wB.y, wB.y);
                ull w6 = pack2(wB.z, wB.z), w7 = pack2(wB.w, wB.w);
                acc01[0] = ffma2(a01, w0, acc01[0]);  acc23[0] = ffma2(a23, w0, acc23[0]);
                acc01[1] = ffma2(a01, w1, acc01[1]);  acc23[1] = ffma2(a23, w1, acc23[1]);
                acc01[2] = ffma2(a01, w2, acc01[2]);  acc23[2] = ffma2(a23, w2, acc23[2]);
                acc01[3] = ffma2(a01, w3, acc01[3]);  acc23[3] = ffma2(a23, w3, acc23[3]);
                acc01[4] = ffma2(a01, w4, acc01[4]);  acc23[4] = ffma2(a23, w4, acc23[4]);
                acc01[5] = ffma2(a01, w5, acc01[5]);  acc23[5] = ffma2(a23, w5, acc23[5]);
                acc01[6] = ffma2(a01, w6, acc01[6]);  acc23[6] = ffma2(a23, w6, acc23[6]);
                acc01[7] = ffma2(a01, w7, acc01[7]);  acc23[7] = ffma2(a23, w7, acc23[7]);
            }
            ull h01[8], h23[8];
            #pragma unroll
            for (int c = 0; c < 8; c++)
                tanh_jvp_pk(acc01[c], acc23[c], &h01[c], &h23[c]);
            __syncthreads();   // all layer-3 reads of Ap/Bp done
            ull* oA = (ull*)Ap;
            ull* oB = (ull*)Bp;
            #pragma unroll
            for (int c = 0; c < 8; c++) {
                oA[(j0 + c) * 32 + lane] = h01[c];
                oB[(j0 + c) * 32 + lane] = h23[c];
            }
        }
        __syncthreads();

        // ---------- Layer 4: 64 -> 1 (4 dots per point) -------------------
        if (tid < 128) {
            const int q = tid >> 5;              // quantity 0..3
            const int p = tid & 31;              // point
            const float2* hb = (q < 2 ? Ap : Bp);
            const bool hi = (q & 1);
            float dot = (q == 0) ? b4v : 0.0f;
            #pragma unroll
            for (int k = 0; k < 64; k++) {
                float2 v = hb[k * 32 + p];
                dot = fmaf(hi ? v.y : v.x, W4s[k], dot);
            }
            out[(tile * 32 + p) * 4 + q] = dot;
        }
        __syncthreads();   // Ap/Bp reads done before next tile overwrites
    }
}

extern "C" void kernel_launch(void* const* d_in, const int* in_sizes, int n_in,
                              void* d_out, int out_size)
{
    const float* x  = (const float*)d_in[0];
    const float* W1 = (const float*)d_in[1];
    const float* b1 = (const float*)d_in[2];
    const float* W2 = (const float*)d_in[3];
    const float* b2 = (const float*)d_in[4];
    const float* W3 = (const float*)d_in[5];
    const float* b3 = (const float*)d_in[6];
    const float* W4 = (const float*)d_in[7];
    const float* b4 = (const float*)d_in[8];
    float* out = (float*)d_out;

    const int N = in_sizes[0] / 3;       // 262144
    const int n_tiles = N / 32;          // 8192

    cudaFuncSetAttribute(pinn_tc2_kernel,
                         cudaFuncAttributeMaxDynamicSharedMemorySize, SMEM_TOTAL);

    pinn_tc2_kernel<<<NSM, TPB, SMEM_TOTAL>>>(
        x, W1, b1, W2, b2, W3, b3, W4, b4, out, n_tiles);
}